// round 2
// baseline (speedup 1.0000x reference)
#include <cuda_runtime.h>
#include <math.h>

#define N_ATOMS   8000
#define N_PAIRS   80000
#define NF        32          // nf_in == nf_out
#define ND        16          // n_dist
#define NC        4           // n_comp
#define SPAN      (ND * NF)   // 512
#define HARD_CUT  6.5f
#define GN_EPS    1e-5f

// ---------------- scratch (device globals; no allocation allowed) -----------
__device__ float g_proj[N_ATOMS * SPAN];    // proj[j][d*32+o]  (16.4 MB)
__device__ float g_sense[N_PAIRS * ND];     // sense[p][d]      (5.1 MB)
__device__ int   g_seg[N_ATOMS + 1];        // segment offsets into sorted pair_first

// ---------------- K0: segment offsets via lower_bound -----------------------
__global__ void seg_kernel(const int* __restrict__ pair_first) {
    int a = blockIdx.x * blockDim.x + threadIdx.x;
    if (a > N_ATOMS) return;
    int lo = 0, hi = N_PAIRS;
    while (lo < hi) {
        int mid = (lo + hi) >> 1;
        if (pair_first[mid] < a) lo = mid + 1; else hi = mid;
    }
    g_seg[a] = lo;
}

// ---------------- K1: per-pair sensitivities --------------------------------
__global__ void sense_kernel(const float* __restrict__ dist,
                             const float* __restrict__ mu,
                             const float* __restrict__ sigma) {
    int t = blockIdx.x * blockDim.x + threadIdx.x;
    if (t >= N_PAIRS * ND) return;
    int p = t >> 4;
    int d = t & 15;
    float dp   = dist[p];
    float invd = 1.0f / dp;
    float z    = (invd - mu[d]) / sigma[d];
    float base = expf(-0.5f * z * z);
    float c    = cosf(0.5f * 3.14159265358979323846f * dp / HARD_CUT);
    float cut  = (dp < HARD_CUT) ? c * c : 0.0f;
    g_sense[t] = base * cut;
}

// ---------------- K2: proj[j,d,o] = sum_f feat[j,f] * W[d,o,f] --------------
// 512 threads: thread = d*32 + o, holds its 32 weights in registers.
#define APB 16   // atoms per block
__global__ __launch_bounds__(512) void proj_kernel(
        const float* __restrict__ feat,
        const float* __restrict__ intw) {
    int tid = threadIdx.x;
    // load this thread's weight row W[d][o][0..31] (flat: tid*32 + f)
    float w[NF];
    const float4* wp = reinterpret_cast<const float4*>(intw + tid * NF);
#pragma unroll
    for (int k = 0; k < NF / 4; k++) {
        float4 v = wp[k];
        w[4 * k + 0] = v.x; w[4 * k + 1] = v.y;
        w[4 * k + 2] = v.z; w[4 * k + 3] = v.w;
    }
    __shared__ float fsh[NF];
    int a0 = blockIdx.x * APB;
#pragma unroll 1
    for (int it = 0; it < APB; it++) {
        int a = a0 + it;
        if (tid < NF) fsh[tid] = feat[a * NF + tid];
        __syncthreads();
        float acc = 0.0f;
#pragma unroll
        for (int f = 0; f < NF; f++) acc = fmaf(w[f], fsh[f], acc);
        g_proj[a * SPAN + tid] = acc;
        __syncthreads();
    }
}

// ---------------- K3: per-atom warp — pair loop + invariants + GN + mix -----
// block = 256 threads = 8 warps, warp w handles atom blockIdx.x*8 + w.
__global__ __launch_bounds__(256) void atom_kernel(
        const float* __restrict__ feat,
        const float* __restrict__ rhat,        // (P,4)
        const int*   __restrict__ pair_second,
        const float* __restrict__ selfw,       // (32,32) [o][f]
        const float* __restrict__ selfb,       // (32)
        const float* __restrict__ mixw,        // (32,2,32) flat k*32+oo, k=o*2+g
        const float* __restrict__ gnw,         // (64) [g*32+o]
        const float* __restrict__ gnb,
        float* __restrict__ out) {
    __shared__ float swsh[NF * NF];            // selfint_w transposed: [f*32 + o]
    __shared__ float xn_sh[8][64];

    // stage selfint_w transposed (conflict-free STS; strided LDG, L1-cached)
    for (int i = threadIdx.x; i < NF * NF; i += 256)
        swsh[i] = selfw[(i & 31) * NF + (i >> 5)];
    __syncthreads();

    int warp = threadIdx.x >> 5;
    int lane = threadIdx.x & 31;
    int a = blockIdx.x * 8 + warp;

    int p0 = g_seg[a], p1 = g_seg[a + 1];

    float tf0 = 0.f, tf1 = 0.f, tf2 = 0.f, tf3 = 0.f;
    for (int p = p0; p < p1; p++) {
        int j = pair_second[p];
        const float* pr = g_proj + j * SPAN + lane;
        const float* sp = g_sense + p * ND;
        float h = 0.f;
#pragma unroll
        for (int d = 0; d < ND; d++) h = fmaf(sp[d], pr[d * NF], h);
        const float4 r = *reinterpret_cast<const float4*>(rhat + p * NC);
        tf0 = fmaf(r.x, h, tf0);
        tf1 = fmaf(r.y, h, tf1);
        tf2 = fmaf(r.z, h, tf2);
        tf3 = fmaf(r.w, h, tf3);
    }

    // invariants
    float inv0 = tf0;
    float inv1 = tf1 * tf1 + tf2 * tf2 + tf3 * tf3;

    // GroupNorm per group across the warp's 32 lanes
    float xn0, xn1;
    {
        float s = inv0, sq = inv0 * inv0;
#pragma unroll
        for (int m = 16; m; m >>= 1) {
            s  += __shfl_xor_sync(0xffffffffu, s,  m);
            sq += __shfl_xor_sync(0xffffffffu, sq, m);
        }
        float mean = s * (1.0f / 32.0f);
        float var  = sq * (1.0f / 32.0f) - mean * mean;
        xn0 = (inv0 - mean) * rsqrtf(var + GN_EPS) * gnw[lane] + gnb[lane];
    }
    {
        float s = inv1, sq = inv1 * inv1;
#pragma unroll
        for (int m = 16; m; m >>= 1) {
            s  += __shfl_xor_sync(0xffffffffu, s,  m);
            sq += __shfl_xor_sync(0xffffffffu, sq, m);
        }
        float mean = s * (1.0f / 32.0f);
        float var  = sq * (1.0f / 32.0f) - mean * mean;
        xn1 = (inv1 - mean) * rsqrtf(var + GN_EPS) * gnw[NF + lane] + gnb[NF + lane];
    }
    // norm_inv layout: k = o*2 + g
    xn_sh[warp][lane * 2 + 0] = xn0;
    xn_sh[warp][lane * 2 + 1] = xn1;
    __syncwarp();

    // mixing GEMV: mix[oo] = sum_k xn[k] * mixw[k*32 + oo]
    float m = 0.f;
#pragma unroll
    for (int k = 0; k < 2 * NF; k++)
        m = fmaf(xn_sh[warp][k], mixw[k * NF + lane], m);

    // self interaction: s = b[oo] + sum_f feat[a,f] * selfw[oo,f]
    float sp = selfb[lane];
    const float* fa = feat + a * NF;
#pragma unroll
    for (int f = 0; f < NF; f++)
        sp = fmaf(fa[f], swsh[f * NF + lane], sp);

    out[a * NF + lane] = m + sp;
}

// ---------------- launch ----------------------------------------------------
extern "C" void kernel_launch(void* const* d_in, const int* in_sizes, int n_in,
                              void* d_out, int out_size) {
    const float* in_features = (const float*)d_in[0];
    const float* tensor_rhats = (const float*)d_in[1];
    const float* dist_pairs = (const float*)d_in[2];
    const float* int_weights = (const float*)d_in[3];
    const float* selfint_w = (const float*)d_in[4];
    const float* selfint_b = (const float*)d_in[5];
    const float* mixing_weights = (const float*)d_in[6];
    const float* gn_weight = (const float*)d_in[7];
    const float* gn_bias = (const float*)d_in[8];
    const float* sens_mu = (const float*)d_in[9];
    const float* sens_sigma = (const float*)d_in[10];
    const int*   pair_first = (const int*)d_in[11];
    const int*   pair_second = (const int*)d_in[12];
    float* out = (float*)d_out;

    seg_kernel<<<(N_ATOMS + 1 + 255) / 256, 256>>>(pair_first);
    sense_kernel<<<(N_PAIRS * ND + 255) / 256, 256>>>(dist_pairs, sens_mu, sens_sigma);
    proj_kernel<<<N_ATOMS / APB, 512>>>(in_features, int_weights);
    atom_kernel<<<N_ATOMS / 8, 256>>>(in_features, tensor_rhats, pair_second,
                                      selfint_w, selfint_b, mixing_weights,
                                      gn_weight, gn_bias, out);
}

// round 3
// speedup vs baseline: 1.7867x; 1.7867x over previous
#include <cuda_runtime.h>
#include <math.h>

#define N_ATOMS   8000
#define N_PAIRS   80000
#define NF        32          // nf_in == nf_out
#define ND        16          // n_dist
#define NC        4           // n_comp
#define SPAN      (ND * NF)   // 512
#define HARD_CUT  6.5f
#define GN_EPS    1e-5f

// ---------------- scratch (device globals; no allocation allowed) -----------
__device__ float g_proj[N_ATOMS * SPAN];    // proj[j][d*32+o]  (16.4 MB)
__device__ float g_h[N_PAIRS * NF];         // h[p][o]          (10.2 MB)

// ---------------- K1: proj[j,d,o] = sum_f feat[j,f] * W[d,o,f] --------------
// 512 threads: thread = d*32+o holds its 32 weights in registers.
// 16 atoms per block, 4 atoms per barrier phase (4 independent accumulators).
#define APB 16
__global__ __launch_bounds__(512) void proj_kernel(
        const float* __restrict__ feat,
        const float* __restrict__ intw) {
    int tid = threadIdx.x;
    float w[NF];
    const float4* wp = reinterpret_cast<const float4*>(intw + tid * NF);
#pragma unroll
    for (int k = 0; k < NF / 4; k++) {
        float4 v = wp[k];
        w[4 * k + 0] = v.x; w[4 * k + 1] = v.y;
        w[4 * k + 2] = v.z; w[4 * k + 3] = v.w;
    }
    __shared__ float fsh[4][NF];
    int a0 = blockIdx.x * APB;
#pragma unroll 1
    for (int it = 0; it < APB; it += 4) {
        if (tid < 128)
            fsh[tid >> 5][tid & 31] = feat[(a0 + it + (tid >> 5)) * NF + (tid & 31)];
        __syncthreads();
        float acc0 = 0.f, acc1 = 0.f, acc2 = 0.f, acc3 = 0.f;
#pragma unroll
        for (int f = 0; f < NF; f++) {
            float wf = w[f];
            acc0 = fmaf(wf, fsh[0][f], acc0);
            acc1 = fmaf(wf, fsh[1][f], acc1);
            acc2 = fmaf(wf, fsh[2][f], acc2);
            acc3 = fmaf(wf, fsh[3][f], acc3);
        }
        g_proj[(a0 + it + 0) * SPAN + tid] = acc0;
        g_proj[(a0 + it + 1) * SPAN + tid] = acc1;
        g_proj[(a0 + it + 2) * SPAN + tid] = acc2;
        g_proj[(a0 + it + 3) * SPAN + tid] = acc3;
        __syncthreads();
    }
}

// ---------------- K2: h[p,o] = sum_d sense[p,d] * proj[j_p,d,o] -------------
// One warp per pair; sense computed in lanes 0..15 and shuffled.
__global__ __launch_bounds__(256) void hpair_kernel(
        const float* __restrict__ dist,
        const float* __restrict__ mu,
        const float* __restrict__ sigma,
        const int* __restrict__ pair_second) {
    int warp = threadIdx.x >> 5;
    int lane = threadIdx.x & 31;
    int p = blockIdx.x * 8 + warp;           // grid = N_PAIRS/8 exact

    float dp = dist[p];                       // uniform
    float sv = 0.0f;
    if (lane < ND) {
        float invd = 1.0f / dp;
        float z    = (invd - mu[lane]) / sigma[lane];
        float base = __expf(-0.5f * z * z);
        float c    = __cosf(0.24166097335f * dp);   // 0.5*pi/6.5
        float cut  = (dp < HARD_CUT) ? c * c : 0.0f;
        sv = base * cut;
    }
    int j = pair_second[p];                   // uniform
    const float* pr = g_proj + j * SPAN + lane;

    float h = 0.0f;
#pragma unroll
    for (int d = 0; d < ND; d++) {
        float s = __shfl_sync(0xffffffffu, sv, d);
        h = fmaf(s, pr[d * NF], h);
    }
    g_h[p * NF + lane] = h;
}

// ---------------- K3: per-atom warp — pair loop + invariants + GN + mix -----
__global__ __launch_bounds__(256) void atom_kernel(
        const float* __restrict__ feat,
        const float* __restrict__ rhat,        // (P,4)
        const int*   __restrict__ pair_first,  // sorted
        const float* __restrict__ selfw,       // (32,32) [o][f]
        const float* __restrict__ selfb,       // (32)
        const float* __restrict__ mixw,        // (64,32) flat k*32+oo, k=o*2+g
        const float* __restrict__ gnw,         // (64) [g*32+o]
        const float* __restrict__ gnb,
        float* __restrict__ out) {
    __shared__ float swsh[NF * NF];            // selfint_w transposed [f*32+o]
    __shared__ float xn_sh[8][64];

    for (int i = threadIdx.x; i < NF * NF; i += 256)
        swsh[i] = selfw[(i & 31) * NF + (i >> 5)];
    __syncthreads();

    int warp = threadIdx.x >> 5;
    int lane = threadIdx.x & 31;
    int a = blockIdx.x * 8 + warp;

    // fused segment search: lanes 0/1 find lower_bound(a), lower_bound(a+1)
    int target = a + (lane & 1);
    int lo = 0, hi = N_PAIRS;
    while (lo < hi) {
        int mid = (lo + hi) >> 1;
        if (pair_first[mid] < target) lo = mid + 1; else hi = mid;
    }
    int p0 = __shfl_sync(0xffffffffu, lo, 0);
    int p1 = __shfl_sync(0xffffffffu, lo, 1);

    float tf0 = 0.f, tf1 = 0.f, tf2 = 0.f, tf3 = 0.f;
    int p = p0;
    for (; p + 1 < p1; p += 2) {
        float ha = g_h[p * NF + lane];
        float hb = g_h[(p + 1) * NF + lane];
        const float4 ra = *reinterpret_cast<const float4*>(rhat + p * NC);
        const float4 rb = *reinterpret_cast<const float4*>(rhat + (p + 1) * NC);
        tf0 = fmaf(ra.x, ha, tf0); tf0 = fmaf(rb.x, hb, tf0);
        tf1 = fmaf(ra.y, ha, tf1); tf1 = fmaf(rb.y, hb, tf1);
        tf2 = fmaf(ra.z, ha, tf2); tf2 = fmaf(rb.z, hb, tf2);
        tf3 = fmaf(ra.w, ha, tf3); tf3 = fmaf(rb.w, hb, tf3);
    }
    if (p < p1) {
        float ha = g_h[p * NF + lane];
        const float4 ra = *reinterpret_cast<const float4*>(rhat + p * NC);
        tf0 = fmaf(ra.x, ha, tf0);
        tf1 = fmaf(ra.y, ha, tf1);
        tf2 = fmaf(ra.z, ha, tf2);
        tf3 = fmaf(ra.w, ha, tf3);
    }

    // invariants
    float inv0 = tf0;
    float inv1 = tf1 * tf1 + tf2 * tf2 + tf3 * tf3;

    // GroupNorm across the warp's 32 lanes (channels)
    float xn0, xn1;
    {
        float s = inv0, sq = inv0 * inv0;
#pragma unroll
        for (int m = 16; m; m >>= 1) {
            s  += __shfl_xor_sync(0xffffffffu, s,  m);
            sq += __shfl_xor_sync(0xffffffffu, sq, m);
        }
        float mean = s * (1.0f / 32.0f);
        float var  = sq * (1.0f / 32.0f) - mean * mean;
        xn0 = (inv0 - mean) * rsqrtf(var + GN_EPS) * gnw[lane] + gnb[lane];
    }
    {
        float s = inv1, sq = inv1 * inv1;
#pragma unroll
        for (int m = 16; m; m >>= 1) {
            s  += __shfl_xor_sync(0xffffffffu, s,  m);
            sq += __shfl_xor_sync(0xffffffffu, sq, m);
        }
        float mean = s * (1.0f / 32.0f);
        float var  = sq * (1.0f / 32.0f) - mean * mean;
        xn1 = (inv1 - mean) * rsqrtf(var + GN_EPS) * gnw[NF + lane] + gnb[NF + lane];
    }
    // norm_inv layout: k = o*2 + g
    xn_sh[warp][lane * 2 + 0] = xn0;
    xn_sh[warp][lane * 2 + 1] = xn1;
    __syncwarp();

    // mixing GEMV
    float m = 0.f;
#pragma unroll
    for (int k = 0; k < 2 * NF; k++)
        m = fmaf(xn_sh[warp][k], mixw[k * NF + lane], m);

    // self interaction
    float sp = selfb[lane];
    const float* fa = feat + a * NF;
#pragma unroll
    for (int f = 0; f < NF; f++)
        sp = fmaf(fa[f], swsh[f * NF + lane], sp);

    out[a * NF + lane] = m + sp;
}

// ---------------- launch ----------------------------------------------------
extern "C" void kernel_launch(void* const* d_in, const int* in_sizes, int n_in,
                              void* d_out, int out_size) {
    const float* in_features    = (const float*)d_in[0];
    const float* tensor_rhats   = (const float*)d_in[1];
    const float* dist_pairs     = (const float*)d_in[2];
    const float* int_weights    = (const float*)d_in[3];
    const float* selfint_w      = (const float*)d_in[4];
    const float* selfint_b      = (const float*)d_in[5];
    const float* mixing_weights = (const float*)d_in[6];
    const float* gn_weight      = (const float*)d_in[7];
    const float* gn_bias        = (const float*)d_in[8];
    const float* sens_mu        = (const float*)d_in[9];
    const float* sens_sigma     = (const float*)d_in[10];
    const int*   pair_first     = (const int*)d_in[11];
    const int*   pair_second    = (const int*)d_in[12];
    float* out = (float*)d_out;

    proj_kernel<<<N_ATOMS / APB, 512>>>(in_features, int_weights);
    hpair_kernel<<<N_PAIRS / 8, 256>>>(dist_pairs, sens_mu, sens_sigma, pair_second);
    atom_kernel<<<N_ATOMS / 8, 256>>>(in_features, tensor_rhats, pair_first,
                                      selfint_w, selfint_b, mixing_weights,
                                      gn_weight, gn_bias, out);
}